// round 7
// baseline (speedup 1.0000x reference)
#include <cuda_runtime.h>

#define BB 8192
#define TT 512
#define KK 12

#define FW_THREADS 128               // 4 warps/block, 16 batches/warp
#define FW_BLOCKS (BB / 16 / 4)      // 128
#define BT_THREADS 32

typedef unsigned long long u64;

// Packed backpointers: row (t,b) = u64; nibble j = best prev tag for tag j at t.
__device__ u64 g_bp[(size_t)TT * BB];                       // 33.5 MB
__device__ __align__(16) float g_final[(size_t)BB * KK];    // [B][12], slot10 = -1e30
__device__ float g_scores_scratch[BB];

// ---------------------------------------------------------------------------
// f32x2 packed helpers. add.rn.f32x2 is bit-exact vs scalar FADD RN.
// ---------------------------------------------------------------------------
__device__ __forceinline__ u64 pack2(float lo, float hi) {
    u64 r; asm("mov.b64 %0, {%1, %2};" : "=l"(r) : "f"(lo), "f"(hi)); return r;
}
__device__ __forceinline__ void unpack2(u64 v, float& lo, float& hi) {
    asm("mov.b64 {%0, %1}, %2;" : "=f"(lo), "=f"(hi) : "l"(v));
}
__device__ __forceinline__ u64 add2(u64 a, u64 b) {
    u64 r; asm("add.rn.f32x2 %0, %1, %2;" : "=l"(r) : "l"(a), "l"(b)); return r;
}

// ---------------------------------------------------------------------------
// First-index-wins select (matches jnp.argmax): >= keeps left; every merge's
// left operand covers strictly smaller indices.
// ---------------------------------------------------------------------------
__device__ __forceinline__ void sel2(float a, int ia, float b, int ib,
                                     float& ov, int& oi) {
    bool p = (a >= b);
    ov = p ? a : b;
    oi = p ? ia : ib;
}

// argmax over candidates 0..9 (i=10,11 provably never win for t>=2:
// trans[:,10] = trans[11,:] = -1000 force prev[10]/row-11 ~1000 below max).
__device__ __forceinline__ void amax10(const float* v, float& bv, int& bi) {
    float s0, s1, s2, s3, s4;
    int   i0, i1, i2, i3, i4;
    sel2(v[0], 0, v[1], 1, s0, i0);
    sel2(v[2], 2, v[3], 3, s1, i1);
    sel2(v[4], 4, v[5], 5, s2, i2);
    sel2(v[6], 6, v[7], 7, s3, i3);
    sel2(v[8], 8, v[9], 9, s4, i4);
    float t0, t1; int k0, k1;
    sel2(s0, i0, s1, i1, t0, k0);
    sel2(s2, i2, s3, i3, t1, k1);
    float u; int ku;
    sel2(t0, k0, t1, k1, u, ku);
    sel2(u, ku, s4, i4, bv, bi);
}

__device__ __forceinline__ void amax12(const float* v, float& bv, int& bi) {
    float s0, s1, s2, s3, s4, s5;
    int   i0, i1, i2, i3, i4, i5;
    sel2(v[0],  0,  v[1],  1,  s0, i0);
    sel2(v[2],  2,  v[3],  3,  s1, i1);
    sel2(v[4],  4,  v[5],  5,  s2, i2);
    sel2(v[6],  6,  v[7],  7,  s3, i3);
    sel2(v[8],  8,  v[9],  9,  s4, i4);
    sel2(v[10], 10, v[11], 11, s5, i5);
    float t0, t1, t2; int k0, k1, k2;
    sel2(s0, i0, s1, i1, t0, k0);
    sel2(s2, i2, s3, i3, t1, k1);
    sel2(s4, i4, s5, i5, t2, k2);
    float u; int ku;
    sel2(t0, k0, t1, k1, u, ku);
    sel2(u, ku, t2, k2, bv, bi);
}

// ---------------------------------------------------------------------------
// Forward: 2 lanes per batch (even: tags 0-4, odd: tags 5-9), 16 batches/warp.
// Exchange via shfl.xor(1) only — no smem, no barriers. Packed f32x2 adds.
// 3-slot emission prefetch queue. Tag 11 computed once at t=511; tag 10 never.
// ---------------------------------------------------------------------------
#define TAGUP(JJ, EV, BEST, AV) do {                                           \
    float v_[10]; float m_;                                                    \
    unpack2(add2(pv0, tcc[(JJ)*5+0]), v_[0], v_[1]);                           \
    unpack2(add2(pv1, tcc[(JJ)*5+1]), v_[2], v_[3]);                           \
    unpack2(add2(pv2, tcc[(JJ)*5+2]), v_[4], v_[5]);                           \
    unpack2(add2(pv3, tcc[(JJ)*5+3]), v_[6], v_[7]);                           \
    unpack2(add2(pv4, tcc[(JJ)*5+4]), v_[8], v_[9]);                           \
    amax10(v_, m_, AV);                                                        \
    BEST = m_ + (EV);                                                          \
} while (0)

#define TAGUP1(JJ, EV, BEST, AV) do {                                          \
    float v_[10]; float m_; int ai_;                                           \
    unpack2(add2(pv0, tcc[(JJ)*5+0]), v_[0], v_[1]);                           \
    unpack2(add2(pv1, tcc[(JJ)*5+1]), v_[2], v_[3]);                           \
    unpack2(add2(pv2, tcc[(JJ)*5+2]), v_[4], v_[5]);                           \
    unpack2(add2(pv3, tcc[(JJ)*5+3]), v_[6], v_[7]);                           \
    unpack2(add2(pv4, tcc[(JJ)*5+4]), v_[8], v_[9]);                           \
    amax10(v_, m_, ai_);                                                       \
    sel2(m_, ai_, p10v + tc10[JJ], 10, m_, ai_);                               \
    AV = ai_; BEST = m_ + (EV);                                                \
} while (0)

#define EXCHANGE() do {                                                        \
    float o0 = __shfl_xor_sync(0xffffffffu, b0_, 1);                           \
    float o1 = __shfl_xor_sync(0xffffffffu, b1_, 1);                           \
    float o2 = __shfl_xor_sync(0xffffffffu, b2_, 1);                           \
    float o3 = __shfl_xor_sync(0xffffffffu, b3_, 1);                           \
    float o4 = __shfl_xor_sync(0xffffffffu, b4_, 1);                           \
    float n0 = half ? o0 : b0_, n1 = half ? o1 : b1_;                          \
    float n2 = half ? o2 : b2_, n3 = half ? o3 : b3_;                          \
    float n4 = half ? o4 : b4_, n5 = half ? b0_ : o0;                          \
    float n6 = half ? b1_ : o1, n7 = half ? b2_ : o2;                          \
    float n8 = half ? b3_ : o3, n9 = half ? b4_ : o4;                          \
    pv0 = pack2(n0, n1); pv1 = pack2(n2, n3); pv2 = pack2(n4, n5);             \
    pv3 = pack2(n6, n7); pv4 = pack2(n8, n9);                                  \
} while (0)

#define BPSTORE(T_, WEXTRA) do {                                               \
    unsigned w_ = (unsigned)((((a4_ * 16 + a3_) * 16 + a2_) * 16 + a1_) * 16   \
                             + a0_) | (WEXTRA);                                \
    unsigned wo_ = __shfl_xor_sync(0xffffffffu, w_, 1);                        \
    if (!half) g_bp[(size_t)(T_) * BB + b] = (u64)w_ | ((u64)wo_ << 20);       \
} while (0)

#define BODY(T_, SLOT_) do {                                                   \
    float4 q0 = Q0f[SLOT_], q1 = Q1f[SLOT_];                                   \
    { int tn_ = (T_) + 3; if (tn_ > TT - 1) tn_ = TT - 1;                      \
      Q0f[SLOT_] = __ldg((const float4*)(em + (size_t)tn_ * KK + off0));       \
      Q1f[SLOT_] = __ldg((const float4*)(em + (size_t)tn_ * KK + off1)); }     \
    float e0_ = half ? q0.y : q0.x, e1_ = half ? q0.z : q0.y;                  \
    float e2_ = half ? q0.w : q0.z, e3_ = half ? q1.x : q0.w;                  \
    float e4_ = half ? q1.y : q1.x;                                            \
    float b0_, b1_, b2_, b3_, b4_; int a0_, a1_, a2_, a3_, a4_;                \
    TAGUP(0, e0_, b0_, a0_); TAGUP(1, e1_, b1_, a1_);                          \
    TAGUP(2, e2_, b2_, a2_); TAGUP(3, e3_, b3_, a3_);                          \
    TAGUP(4, e4_, b4_, a4_);                                                   \
    BPSTORE(T_, 0u);                                                           \
    EXCHANGE();                                                                \
} while (0)

__global__ __launch_bounds__(FW_THREADS, 1) void viterbi_fwd(
    const float* __restrict__ logits,   // [B, T, K]
    const float* __restrict__ trans)    // [K, K], trans[i*K+j] = i -> j
{
    const int lane = threadIdx.x & 31;
    const int warp = threadIdx.x >> 5;
    const int p = lane >> 1;
    const int half = lane & 1;          // 0: tags 0-4, 1: tags 5-9
    const size_t b = (((size_t)blockIdx.x * 4 + warp) << 4) + p;
    const int jb = half * 5;
    const int off0 = half * 4, off1 = half * 4 + 4;

    // Packed transition pairs: tcc[jj*5+ii] = (trans[2ii][jb+jj], trans[2ii+1][jb+jj])
    u64 tcc[25];
#pragma unroll
    for (int jj = 0; jj < 5; jj++)
#pragma unroll
        for (int ii = 0; ii < 5; ii++)
            tcc[jj * 5 + ii] = pack2(__ldg(trans + (2 * ii) * KK + jb + jj),
                                     __ldg(trans + (2 * ii + 1) * KK + jb + jj));
    float tc10[5];
#pragma unroll
    for (int jj = 0; jj < 5; jj++) tc10[jj] = __ldg(trans + 10 * KK + jb + jj);
    float tcl[10];
#pragma unroll
    for (int i = 0; i < 10; i++) tcl[i] = __ldg(trans + i * KK + 11);

    const float* em = logits + b * TT * KK;

    // Row 0 + row 1 + queue rows 2,3,4 (slots t%3: 2,0,1)
    float4 z0 = __ldg((const float4*)(em + off0));
    float4 z1 = __ldg((const float4*)(em + off1));
    float4 r1q0 = __ldg((const float4*)(em + KK + off0));
    float4 r1q1 = __ldg((const float4*)(em + KK + off1));
    float4 Q0f[3], Q1f[3];
    Q0f[2] = __ldg((const float4*)(em + 2 * KK + off0));
    Q1f[2] = __ldg((const float4*)(em + 2 * KK + off1));
    Q0f[0] = __ldg((const float4*)(em + 3 * KK + off0));
    Q1f[0] = __ldg((const float4*)(em + 3 * KK + off1));
    Q0f[1] = __ldg((const float4*)(em + 4 * KK + off0));
    Q1f[1] = __ldg((const float4*)(em + 4 * KK + off1));

    // Assemble row-0 prev values p0..p9 (+ p10 for the t=1 peel)
    float s1 = __shfl_xor_sync(0xffffffffu, z0.x, 1);
    float s2 = __shfl_xor_sync(0xffffffffu, z0.y, 1);
    float s3 = __shfl_xor_sync(0xffffffffu, z0.z, 1);
    float s4 = __shfl_xor_sync(0xffffffffu, z0.w, 1);
    float s5 = __shfl_xor_sync(0xffffffffu, z1.x, 1);
    float s6 = __shfl_xor_sync(0xffffffffu, z1.y, 1);
    float s7 = __shfl_xor_sync(0xffffffffu, z1.z, 1);
    float p0 = half ? s1 : z0.x, p1 = half ? s2 : z0.y;
    float p2 = half ? s3 : z0.z, p3 = half ? s4 : z0.w;
    float p4 = half ? z0.x : z1.x, p5 = half ? z0.y : z1.y;
    float p6 = half ? z0.z : z1.z, p7 = half ? z0.w : z1.w;
    float p8 = half ? z1.x : s5, p9 = half ? z1.y : s6;
    const float p10v = half ? z1.z : s7;

    u64 pv0 = pack2(p0, p1), pv1 = pack2(p2, p3), pv2 = pack2(p4, p5);
    u64 pv3 = pack2(p6, p7), pv4 = pack2(p8, p9);

    // ---- peeled t = 1 (extra candidate i = 10 = START) ----
    {
        float4 q0 = r1q0, q1 = r1q1;
        float e0_ = half ? q0.y : q0.x, e1_ = half ? q0.z : q0.y;
        float e2_ = half ? q0.w : q0.z, e3_ = half ? q1.x : q0.w;
        float e4_ = half ? q1.y : q1.x;
        float b0_, b1_, b2_, b3_, b4_; int a0_, a1_, a2_, a3_, a4_;
        TAGUP1(0, e0_, b0_, a0_); TAGUP1(1, e1_, b1_, a1_);
        TAGUP1(2, e2_, b2_, a2_); TAGUP1(3, e3_, b3_, a3_);
        TAGUP1(4, e4_, b4_, a4_);
        BPSTORE(1, 0u);
        EXCHANGE();
    }

    // ---- main loop t = 2..510 ----
#pragma unroll 1
    for (int tb = 2; tb <= 506; tb += 3) {
        BODY(tb + 0, 2);
        BODY(tb + 1, 0);
        BODY(tb + 2, 1);
    }
    BODY(509, 2);
    BODY(510, 0);

    // ---- peeled t = 511 (also computes tag 11 from row 510) ----
    {
        float4 q0 = Q0f[1], q1 = Q1f[1];   // row 511
        float e0_ = half ? q0.y : q0.x, e1_ = half ? q0.z : q0.y;
        float e2_ = half ? q0.w : q0.z, e3_ = half ? q1.x : q0.w;
        float e4_ = half ? q1.y : q1.x;
        float b0_, b1_, b2_, b3_, b4_; int a0_, a1_, a2_, a3_, a4_;
        TAGUP(0, e0_, b0_, a0_); TAGUP(1, e1_, b1_, a1_);
        TAGUP(2, e2_, b2_, a2_); TAGUP(3, e3_, b3_, a3_);
        TAGUP(4, e4_, b4_, a4_);

        // tag 11 chain (uses pv = row 510); q1.w on odd lanes = em[511][11]
        float c_[10];
        {
            float q0f, q1f;
            unpack2(pv0, c_[0], c_[1]); unpack2(pv1, c_[2], c_[3]);
            unpack2(pv2, c_[4], c_[5]); unpack2(pv3, c_[6], c_[7]);
            unpack2(pv4, c_[8], c_[9]);
            (void)q0f; (void)q1f;
        }
#pragma unroll
        for (int i = 0; i < 10; i++) c_[i] = c_[i] + tcl[i];
        float m11; int a11;
        amax10(c_, m11, a11);
        float b11 = m11 + q1.w;

        BPSTORE(511, half ? ((unsigned)a11 << 24) : 0u);

        // final row for scores / last tag
        float* gf = g_final + b * KK;
        if (!half) {
            *(float4*)gf = make_float4(b0_, b1_, b2_, b3_);
            gf[4] = b4_;
        } else {
            gf[5] = b0_;
            *(float2*)(gf + 6) = make_float2(b1_, b2_);
            *(float4*)(gf + 8) = make_float4(b3_, b4_, -1e30f, b11);
        }
    }
}

// ---------------------------------------------------------------------------
// Backtrace (R4 version): one thread per batch; 3-group-deep (48-load) software
// pipeline; STG.128 path writes.
// ---------------------------------------------------------------------------
#define PROC(Rarr, TBASE, CNT)                                                 \
    do {                                                                       \
        _Pragma("unroll") for (int i = 0; i < (CNT); i++) {                    \
            const int tt = (TBASE) - i;                                        \
            const int nx = (int)((Rarr[i] >> (cur * 4)) & 15ull);              \
            pbuf[(tt - 1) & 3] = (float)nx;                                    \
            if (((tt - 1) & 3) == 0)                                           \
                *(float4*)(po + (tt - 1)) =                                    \
                    make_float4(pbuf[0], pbuf[1], pbuf[2], pbuf[3]);           \
            cur = nx;                                                          \
        }                                                                      \
    } while (0)

#define LOADG(Rarr, GIDX)                                                      \
    do {                                                                       \
        if ((GIDX) < 32) {                                                     \
            const int ts = 511 - 16 * (GIDX);                                  \
            _Pragma("unroll") for (int i = 0; i < 16; i++)                     \
                Rarr[i] = __ldg(bp + (size_t)(ts - i) * BB + b);               \
        }                                                                      \
    } while (0)

__global__ __launch_bounds__(BT_THREADS) void viterbi_btr(
    float* __restrict__ scores,   // [B]
    float* __restrict__ paths)    // [B, T] as float
{
    const size_t b = (size_t)blockIdx.x * BT_THREADS + threadIdx.x;

    float v[12];
    {
        const float4* row = (const float4*)(g_final + b * KK);
        float4 r0 = __ldg(&row[0]), r1 = __ldg(&row[1]), r2 = __ldg(&row[2]);
        v[0] = r0.x; v[1] = r0.y; v[2]  = r0.z; v[3]  = r0.w;
        v[4] = r1.x; v[5] = r1.y; v[6]  = r1.z; v[7]  = r1.w;
        v[8] = r2.x; v[9] = r2.y; v[10] = r2.z; v[11] = r2.w;
    }
    float bv; int cur;
    amax12(v, bv, cur);
    scores[b] = bv;

    float* po = paths + b * TT;
    float pbuf[4];
    pbuf[3] = (float)cur;   // path[T-1]

    const u64* bp = g_bp;

    u64 R0[16], R1[16], R2[16];
    LOADG(R0, 0);
    LOADG(R1, 1);
    LOADG(R2, 2);

#pragma unroll 1
    for (int m = 0; m < 10; m++) {
        const int g0 = 3 * m;
        PROC(R0, 511 - 16 * g0, 16);        LOADG(R0, g0 + 3);
        PROC(R1, 511 - 16 * (g0 + 1), 16);  LOADG(R1, g0 + 4);
        PROC(R2, 511 - 16 * (g0 + 2), 16);  LOADG(R2, g0 + 5);
    }
    PROC(R0, 511 - 16 * 30, 16);   // group 30: t = 31..16
    PROC(R1, 511 - 16 * 31, 15);   // group 31 (tail): t = 15..1
}

// ---------------------------------------------------------------------------
// Launch
// ---------------------------------------------------------------------------
extern "C" void kernel_launch(void* const* d_in, const int* in_sizes, int n_in,
                              void* d_out, int out_size) {
    const float* logits = (const float*)d_in[0];
    const float* trans  = (const float*)d_in[1];
    if (n_in >= 2 && in_sizes[0] == KK * KK) {  // robustness: swapped inputs
        const float* tmp = logits; logits = trans; trans = tmp;
    }

    viterbi_fwd<<<FW_BLOCKS, FW_THREADS>>>(logits, trans);

    float* out = (float*)d_out;
    float* scores;
    float* paths;
    float* d_scores_scratch = nullptr;
    cudaGetSymbolAddress((void**)&d_scores_scratch, g_scores_scratch);

    if (out_size >= BB * TT + BB) {
        scores = out;            // [scores (B) | paths (B*T)]
        paths = out + BB;
    } else if (out_size == BB * TT) {
        scores = d_scores_scratch;
        paths = out;
    } else {
        scores = out;
        float* d_bp = nullptr;
        cudaGetSymbolAddress((void**)&d_bp, g_bp);
        paths = (float*)d_bp;    // dead scratch as sink
    }

    viterbi_btr<<<BB / BT_THREADS, BT_THREADS>>>(scores, paths);
}

// round 8
// speedup vs baseline: 1.6143x; 1.6143x over previous
#include <cuda_runtime.h>

#define BB 8192
#define TT 512
#define KK 12

#define GPB 12                       // batches per block (3 groups x 4 warps)
#define FW_THREADS 128
#define NBLK ((BB + GPB - 1) / GPB)  // 683
#define AMASK 0x3fffffffu            // lanes 0..29 active
#define BT_THREADS 32

typedef unsigned long long u64;

// Packed backpointers: row (t,b) = u64; nibble j = best prev tag for tag j at t.
__device__ u64 g_bp[(size_t)TT * BB];                       // 33.5 MB
__device__ __align__(16) float g_final[(size_t)BB * KK];    // [B][12], slot10 = -1e30
__device__ float g_scores_scratch[BB];

// ---------------------------------------------------------------------------
// f32x2 packed helpers. add.rn.f32x2 is bit-exact vs scalar FADD RN.
// ---------------------------------------------------------------------------
__device__ __forceinline__ u64 pack2(float lo, float hi) {
    u64 r; asm("mov.b64 %0, {%1, %2};" : "=l"(r) : "f"(lo), "f"(hi)); return r;
}
__device__ __forceinline__ void unpack2(u64 v, float& lo, float& hi) {
    asm("mov.b64 {%0, %1}, %2;" : "=f"(lo), "=f"(hi) : "l"(v));
}
__device__ __forceinline__ u64 add2(u64 a, u64 b) {
    u64 r; asm("add.rn.f32x2 %0, %1, %2;" : "=l"(r) : "l"(a), "l"(b)); return r;
}

// ---------------------------------------------------------------------------
// First-index-wins select (matches jnp.argmax): >= keeps left; every merge's
// left operand covers strictly smaller indices.
// ---------------------------------------------------------------------------
__device__ __forceinline__ void sel2(float a, int ia, float b, int ib,
                                     float& ov, int& oi) {
    bool p = (a >= b);
    ov = p ? a : b;
    oi = p ? ia : ib;
}

// argmax over candidates 0..9 (i=10,11 provably never win for t>=2:
// trans[:,10] = trans[11,:] = -1000 keep prev[10]/row-11 ~1000 below max).
__device__ __forceinline__ void amax10(const float* v, float& bv, int& bi) {
    float s0, s1, s2, s3, s4;
    int   i0, i1, i2, i3, i4;
    sel2(v[0], 0, v[1], 1, s0, i0);
    sel2(v[2], 2, v[3], 3, s1, i1);
    sel2(v[4], 4, v[5], 5, s2, i2);
    sel2(v[6], 6, v[7], 7, s3, i3);
    sel2(v[8], 8, v[9], 9, s4, i4);
    float t0, t1; int k0, k1;
    sel2(s0, i0, s1, i1, t0, k0);
    sel2(s2, i2, s3, i3, t1, k1);
    float u; int ku;
    sel2(t0, k0, t1, k1, u, ku);
    sel2(u, ku, s4, i4, bv, bi);
}

__device__ __forceinline__ void amax12(const float* v, float& bv, int& bi) {
    float s0, s1, s2, s3, s4, s5;
    int   i0, i1, i2, i3, i4, i5;
    sel2(v[0],  0,  v[1],  1,  s0, i0);
    sel2(v[2],  2,  v[3],  3,  s1, i1);
    sel2(v[4],  4,  v[5],  5,  s2, i2);
    sel2(v[6],  6,  v[7],  7,  s3, i3);
    sel2(v[8],  8,  v[9],  9,  s4, i4);
    sel2(v[10], 10, v[11], 11, s5, i5);
    float t0, t1, t2; int k0, k1, k2;
    sel2(s0, i0, s1, i1, t0, k0);
    sel2(s2, i2, s3, i3, t1, k1);
    sel2(s4, i4, s5, i5, t2, k2);
    float u; int ku;
    sel2(t0, k0, t1, k1, u, ku);
    sel2(u, ku, t2, k2, bv, bi);
}

// ---------------------------------------------------------------------------
// Forward: 1 tag per lane, 10 lanes per batch, 3 batches per warp (lanes 30,31
// idle), 4 warps/block. Warp-local smem exchange (__syncwarp only). Packed
// f32x2 adds (fma pipe). 3-slot emission prefetch. 6x unrolled loop so buffer
// parity + prefetch slot are compile-time. Tag 11 once at t=511; tag 10 never.
// ---------------------------------------------------------------------------
#define FSTEP(T_, S_, PB_, CB_) do {                                           \
    __syncwarp(AMASK);                                                         \
    const u64* rp_ = (const u64*)&buf[PB_][g][0];                              \
    u64 r0_ = rp_[0], r1_ = rp_[1], r2_ = rp_[2], r3_ = rp_[3], r4_ = rp_[4];  \
    const float e_ = en[S_];                                                   \
    { int tn_ = (T_) + 3; if (tn_ > TT - 1) tn_ = TT - 1;                      \
      en[S_] = __ldg(em + (size_t)tn_ * KK + k); }                             \
    float v_[10];                                                              \
    unpack2(add2(r0_, tcp[0]), v_[0], v_[1]);                                  \
    unpack2(add2(r1_, tcp[1]), v_[2], v_[3]);                                  \
    unpack2(add2(r2_, tcp[2]), v_[4], v_[5]);                                  \
    unpack2(add2(r3_, tcp[3]), v_[6], v_[7]);                                  \
    unpack2(add2(r4_, tcp[4]), v_[8], v_[9]);                                  \
    float m_; int a_;                                                          \
    amax10(v_, m_, a_);                                                        \
    best = m_ + e_;                                                            \
    buf[CB_][g][k] = best;                                                     \
    unsigned pa_ = __shfl_xor_sync(AMASK, (unsigned)a_, 1);                    \
    if (!(k & 1))                                                              \
        bp8[((size_t)(T_) * BB + b) * 8 + (k >> 1)] =                          \
            (unsigned char)((unsigned)a_ | (pa_ << 4));                        \
} while (0)

__global__ __launch_bounds__(FW_THREADS) void viterbi_fwd(
    const float* __restrict__ logits,   // [B, T, K]
    const float* __restrict__ trans)    // [K, K], trans[i*K+j] = i -> j
{
    __shared__ __align__(16) float buf[2][GPB][12];   // 48B rows

    const int lane = threadIdx.x & 31;
    const int warp = threadIdx.x >> 5;
    if (lane >= 30) return;
    const int gl = lane / 10;
    const int k = lane - gl * 10;            // tag j = k (0..9)
    const int g = warp * 3 + gl;
    size_t b = (size_t)blockIdx.x * GPB + g;
    if (b >= BB) b = BB - 1;                 // tail duplicates (same-value writes)

    // Packed transition pairs: tcp[ii] = (trans[2ii][k], trans[2ii+1][k])
    u64 tcp[5];
#pragma unroll
    for (int ii = 0; ii < 5; ii++)
        tcp[ii] = pack2(__ldg(trans + (2 * ii) * KK + k),
                        __ldg(trans + (2 * ii + 1) * KK + k));
    const float tc10 = __ldg(trans + 10 * KK + k);   // t=1-only candidate

    const float* em = logits + b * TT * KK;
    unsigned char* bp8 = (unsigned char*)g_bp;

    // t=0 row = emissions (tags 0..9; slot 10 for the t=1 peel)
    buf[0][g][k] = __ldg(em + k);
    if (k == 0) buf[0][g][10] = __ldg(em + 10);
    // emission prefetch: en[s] holds row r with s = (r-1)%3; init rows 1..3
    float en[3];
    en[0] = __ldg(em + 1 * KK + k);
    en[1] = __ldg(em + 2 * KK + k);
    en[2] = __ldg(em + 3 * KK + k);

    float best;

    // ---- peeled t = 1 (extra candidate i = 10 = START) ----
    {
        __syncwarp(AMASK);
        const u64* rp = (const u64*)&buf[0][g][0];
        u64 r0 = rp[0], r1 = rp[1], r2 = rp[2], r3 = rp[3], r4 = rp[4];
        const float em10 = buf[0][g][10];
        const float e = en[0];
        en[0] = __ldg(em + 4 * KK + k);      // row 4 -> slot 0

        float v[10];
        unpack2(add2(r0, tcp[0]), v[0], v[1]);
        unpack2(add2(r1, tcp[1]), v[2], v[3]);
        unpack2(add2(r2, tcp[2]), v[4], v[5]);
        unpack2(add2(r3, tcp[3]), v[6], v[7]);
        unpack2(add2(r4, tcp[4]), v[8], v[9]);
        float m; int a;
        amax10(v, m, a);
        sel2(m, a, em10 + tc10, 10, m, a);

        best = m + e;
        buf[1][g][k] = best;
        unsigned pa = __shfl_xor_sync(AMASK, (unsigned)a, 1);
        if (!(k & 1))
            bp8[((size_t)1 * BB + b) * 8 + (k >> 1)] =
                (unsigned char)((unsigned)a | (pa << 4));
    }

    // ---- main loop t = 2..511, unrolled by 6 (85 chunks exactly) ----
#pragma unroll 1
    for (int tb = 2; tb <= TT - 6; tb += 6) {
        FSTEP(tb + 0, 1, 1, 0);
        FSTEP(tb + 1, 2, 0, 1);
        FSTEP(tb + 2, 0, 1, 0);
        FSTEP(tb + 3, 1, 0, 1);
        FSTEP(tb + 4, 2, 1, 0);
        FSTEP(tb + 5, 0, 0, 1);
    }

    // final row for scores / last tag (tags 0..9)
    g_final[b * KK + k] = best;

    // lane k==0: tag 11 at t=511 from row 510 (buf[0]; synced in step 511)
    if (k == 0) {
        float tcl[10];
#pragma unroll
        for (int i = 0; i < 10; i++) tcl[i] = __ldg(trans + i * KK + 11);
        const u64* rp = (const u64*)&buf[0][g][0];
        float c[10];
        unpack2(rp[0], c[0], c[1]);
        unpack2(rp[1], c[2], c[3]);
        unpack2(rp[2], c[4], c[5]);
        unpack2(rp[3], c[6], c[7]);
        unpack2(rp[4], c[8], c[9]);
#pragma unroll
        for (int i = 0; i < 10; i++) c[i] = c[i] + tcl[i];
        float m11; int a11;
        amax10(c, m11, a11);
        float b11 = m11 + __ldg(em + (size_t)(TT - 1) * KK + 11);
        g_final[b * KK + 10] = -1e30f;
        g_final[b * KK + 11] = b11;
        bp8[((size_t)(TT - 1) * BB + b) * 8 + 5] = (unsigned char)(a11 << 4);
    }
}

// ---------------------------------------------------------------------------
// Backtrace (proven R4 version): one thread per batch; 3-group-deep (48-load)
// software pipeline; STG.128 path writes.
// ---------------------------------------------------------------------------
#define PROC(Rarr, TBASE, CNT)                                                 \
    do {                                                                       \
        _Pragma("unroll") for (int i = 0; i < (CNT); i++) {                    \
            const int tt = (TBASE) - i;                                        \
            const int nx = (int)((Rarr[i] >> (cur * 4)) & 15ull);              \
            pbuf[(tt - 1) & 3] = (float)nx;                                    \
            if (((tt - 1) & 3) == 0)                                           \
                *(float4*)(po + (tt - 1)) =                                    \
                    make_float4(pbuf[0], pbuf[1], pbuf[2], pbuf[3]);           \
            cur = nx;                                                          \
        }                                                                      \
    } while (0)

#define LOADG(Rarr, GIDX)                                                      \
    do {                                                                       \
        if ((GIDX) < 32) {                                                     \
            const int ts = 511 - 16 * (GIDX);                                  \
            _Pragma("unroll") for (int i = 0; i < 16; i++)                     \
                Rarr[i] = __ldg(bp + (size_t)(ts - i) * BB + b);               \
        }                                                                      \
    } while (0)

__global__ __launch_bounds__(BT_THREADS) void viterbi_btr(
    float* __restrict__ scores,   // [B]
    float* __restrict__ paths)    // [B, T] as float
{
    const size_t b = (size_t)blockIdx.x * BT_THREADS + threadIdx.x;

    float v[12];
    {
        const float4* row = (const float4*)(g_final + b * KK);
        float4 r0 = __ldg(&row[0]), r1 = __ldg(&row[1]), r2 = __ldg(&row[2]);
        v[0] = r0.x; v[1] = r0.y; v[2]  = r0.z; v[3]  = r0.w;
        v[4] = r1.x; v[5] = r1.y; v[6]  = r1.z; v[7]  = r1.w;
        v[8] = r2.x; v[9] = r2.y; v[10] = r2.z; v[11] = r2.w;
    }
    float bv; int cur;
    amax12(v, bv, cur);
    scores[b] = bv;

    float* po = paths + b * TT;
    float pbuf[4];
    pbuf[3] = (float)cur;   // path[T-1]

    const u64* bp = g_bp;

    u64 R0[16], R1[16], R2[16];
    LOADG(R0, 0);
    LOADG(R1, 1);
    LOADG(R2, 2);

#pragma unroll 1
    for (int m = 0; m < 10; m++) {
        const int g0 = 3 * m;
        PROC(R0, 511 - 16 * g0, 16);        LOADG(R0, g0 + 3);
        PROC(R1, 511 - 16 * (g0 + 1), 16);  LOADG(R1, g0 + 4);
        PROC(R2, 511 - 16 * (g0 + 2), 16);  LOADG(R2, g0 + 5);
    }
    PROC(R0, 511 - 16 * 30, 16);   // group 30: t = 31..16
    PROC(R1, 511 - 16 * 31, 15);   // group 31 (tail): t = 15..1
}

// ---------------------------------------------------------------------------
// Launch
// ---------------------------------------------------------------------------
extern "C" void kernel_launch(void* const* d_in, const int* in_sizes, int n_in,
                              void* d_out, int out_size) {
    const float* logits = (const float*)d_in[0];
    const float* trans  = (const float*)d_in[1];
    if (n_in >= 2 && in_sizes[0] == KK * KK) {  // robustness: swapped inputs
        const float* tmp = logits; logits = trans; trans = tmp;
    }

    viterbi_fwd<<<NBLK, FW_THREADS>>>(logits, trans);

    float* out = (float*)d_out;
    float* scores;
    float* paths;
    float* d_scores_scratch = nullptr;
    cudaGetSymbolAddress((void**)&d_scores_scratch, g_scores_scratch);

    if (out_size >= BB * TT + BB) {
        scores = out;            // [scores (B) | paths (B*T)]
        paths = out + BB;
    } else if (out_size == BB * TT) {
        scores = d_scores_scratch;
        paths = out;
    } else {
        scores = out;
        float* d_bp = nullptr;
        cudaGetSymbolAddress((void**)&d_bp, g_bp);
        paths = (float*)d_bp;    // dead scratch as sink
    }

    viterbi_btr<<<BB / BT_THREADS, BT_THREADS>>>(scores, paths);
}